// round 14
// baseline (speedup 1.0000x reference)
#include <cuda_runtime.h>
#include <cuda_fp16.h>
#include <cstdint>
#include <math.h>

// DiagBlockAttention b=16,t=8192,e=256,block=128 — mma.sync fp16 single-pass.
// R14: R13 + cp.async 2-deep V pipeline (self-consistent thread mapping, V0/V1
// issued during phase-1 tail) + streaming stores for O/A.
// d_out = O [b,t,256] fp32 ++ A_flat [b,t,128] fp32.

namespace {
constexpr int Tt = 8192, Ee = 256, BSz = 128, NBk = 64;
constexpr float SCALE = 0.0625f;
constexpr int EC = 32;           // phase-1 e-chunk
constexpr int VC = 32;           // phase-3 e-chunk
constexpr int NT = 256;

// SMEM byte map
// fp16 Q/K tiles [128 r][32 c], 64B rows (swz64), double buffered:
//   BF0 + bs*16384 (Qh +0, Kh +8192)
constexpr int BF0   = 0;
// raw fp32 QK staging, double-buffered: RAW0 + bs*32768 (Q +0, K +16384)
constexpr int RAW0  = 32768;
// raw fp32 V chunks [128 tok][32 e] (swz128 rows of 128B), double buffered at
//   RAWV0 + bs*16384 — overlays rawQK[0] (dead after convert1(6) + barrier 6)
constexpr int RAWV0 = 32768;
// V^T fp16 [32 e][128 tok], 256B rows (swz256), double buffered at
//   VF0 + bs*8192 — overlays rawQK[1] (dead after convert1(7) + barrier 7)
constexpr int VF0   = 65536;
constexpr int SMEM_BYTES = 98304;   // 96 KB -> 2 CTAs/SM
}

__device__ __forceinline__ uint32_t swz64(uint32_t o)  { return o ^ ((o >> 3) & 0x30u); }
__device__ __forceinline__ uint32_t swz128(uint32_t o) { return o ^ ((o >> 3) & 0x70u); }
__device__ __forceinline__ uint32_t swz256(uint32_t o) { return o ^ ((o >> 4) & 0x70u); }

__device__ __forceinline__ uint32_t smem_u32(const void* p) {
    uint32_t a;
    asm("{ .reg .u64 t; cvta.to.shared.u64 t, %1; cvt.u32.u64 %0, t; }" : "=r"(a) : "l"(p));
    return a;
}

__device__ __forceinline__ void cpasync16(uint32_t dst, const void* src) {
    asm volatile("cp.async.ca.shared.global [%0], [%1], 16;" :: "r"(dst), "l"(src) : "memory");
}
__device__ __forceinline__ void cpcommit() {
    asm volatile("cp.async.commit_group;" ::: "memory");
}
template <int N>
__device__ __forceinline__ void cpwait() {
    asm volatile("cp.async.wait_group %0;" :: "n"(N) : "memory");
}

__device__ __forceinline__ void ldmx4(uint32_t r[4], uint32_t addr) {
    asm volatile("ldmatrix.sync.aligned.m8n8.x4.shared.b16 {%0,%1,%2,%3}, [%4];"
                 : "=r"(r[0]), "=r"(r[1]), "=r"(r[2]), "=r"(r[3]) : "r"(addr));
}

__device__ __forceinline__ void mma16816(float c[4], const uint32_t a[4],
                                         uint32_t b0, uint32_t b1) {
    asm volatile("mma.sync.aligned.m16n8k16.row.col.f32.f16.f16.f32 "
                 "{%0,%1,%2,%3},{%4,%5,%6,%7},{%8,%9},{%0,%1,%2,%3};"
                 : "+f"(c[0]), "+f"(c[1]), "+f"(c[2]), "+f"(c[3])
                 : "r"(a[0]), "r"(a[1]), "r"(a[2]), "r"(a[3]), "r"(b0), "r"(b1));
}

// Pack two fp32 into fp16x2 (lo = x, hi = y), round-to-nearest.
__device__ __forceinline__ uint32_t packh2(float x, float y) {
    uint32_t r;
    asm("cvt.rn.f16x2.f32 %0, %1, %2;" : "=r"(r) : "f"(y), "f"(x));
    return r;
}

// Streaming (evict-first) global store of a float2.
__device__ __forceinline__ void stcs2(float* p, float x, float y) {
    asm volatile("st.global.cs.v2.f32 [%0], {%1, %2};" :: "l"(p), "f"(x), "f"(y) : "memory");
}

__global__ void __launch_bounds__(NT, 2)
diag_block_attn_mma(const float* __restrict__ Q, const float* __restrict__ K,
                    const float* __restrict__ V, float* __restrict__ Out,
                    float* __restrict__ Afl)
{
    extern __shared__ char smc[];
    const uint32_t sb = smem_u32(smc);

    const int tid = threadIdx.x;
    const int wid = tid >> 5;        // 0..7
    const int lid = tid & 31;
    const int g   = lid >> 2;
    const int tg  = lid & 3;
    const int wm  = wid;             // warp row band: rows wm*16..+15
    const int lr  = lid & 15;
    const int lc  = (lid >> 4) * 8;  // ldmatrix col-block (elements)
    const int n   = blockIdx.x;
    const int b   = blockIdx.y;
    const long base = ((long)b * Tt + (long)n * BSz) * Ee;

    // Causal: 16-wide col-tile ng kept iff ng <= wm (also phase-3 k-tiles).
    const int ngEnd = wm + 1;

    // V-pipeline per-thread coords: token k, e-quarter eq (self-consistent:
    // the thread that cp.asyncs a segment is the thread that LDS-reads it).
    const int vk = lid + 32 * (wid & 3);    // token 0..127

    // ---- phase-1: cp.async raw fp32 QK chunk c -> raw buffer bs ----
    auto cpstage1 = [&](int c, int bs) {
        const float* Qg = Q + base + c * EC;
        const float* Kg = K + base + c * EC;
        const uint32_t rw = sb + RAW0 + bs * 32768;
        #pragma unroll
        for (int u = 0; u < 4; ++u) {
            int idx = tid + NT * u;        // 0..1023
            int r   = idx >> 3;            // 0..127
            int s   = idx & 7;             // 16B segment
            cpasync16(rw + r * 128 + s * 16,         Qg + (long)r * Ee + s * 4);
            cpasync16(rw + 16384 + r * 128 + s * 16, Kg + (long)r * Ee + s * 4);
        }
        cpcommit();
    };

    // ---- phase-1: convert raw buffer rbs -> fp16 tile buffer (same idx map) --
    auto convert1 = [&](int bs) {
        const char* rw = smc + RAW0 + bs * 32768;
        char* fb = smc + BF0 + bs * 16384;
        #pragma unroll
        for (int u = 0; u < 4; ++u) {
            int idx = tid + NT * u;        // 0..1023
            int r   = idx >> 3;
            int ce  = (idx & 7) << 2;
            float4 q = *reinterpret_cast<const float4*>(rw + r * 128 + ce * 4);
            float4 k = *reinterpret_cast<const float4*>(rw + 16384 + r * 128 + ce * 4);
            uint32_t off = swz64((uint32_t)(r * 64 + ce * 2));
            *reinterpret_cast<uint2*>(fb + off) =
                make_uint2(packh2(q.x, q.y), packh2(q.z, q.w));
            *reinterpret_cast<uint2*>(fb + 8192 + off) =
                make_uint2(packh2(k.x, k.y), packh2(k.z, k.w));
        }
    };

    // ---- V pipeline: cp.async raw V chunk m -> rawV[m&1] (swz128 rows) ----
    auto cpstageV = [&](int m) {
        const float* Vg = V + base + m * VC;
        const uint32_t rv = sb + RAWV0 + (m & 1) * 16384;
        #pragma unroll
        for (int u = 0; u < 2; ++u) {
            int eq = (wid >> 2) + 2 * u;   // e-quarter 0..3
            cpasync16(rv + swz128((uint32_t)(vk * 128 + eq * 32)),
                      Vg + (long)vk * Ee + eq * 8);
            cpasync16(rv + swz128((uint32_t)(vk * 128 + eq * 32 + 16)),
                      Vg + (long)vk * Ee + eq * 8 + 4);
        }
        cpcommit();
    };

    // ---- V pipeline: convert rawV[m&1] -> transposed fp16 VF[m&1] ----
    auto convertV = [&](int m) {
        const char* rv = smc + RAWV0 + (m & 1) * 16384;
        char* vf = smc + VF0 + (m & 1) * 8192;
        #pragma unroll
        for (int u = 0; u < 2; ++u) {
            int eq = (wid >> 2) + 2 * u;
            int e0 = 8 * eq;
            float4 a = *reinterpret_cast<const float4*>(
                rv + swz128((uint32_t)(vk * 128 + e0 * 4)));
            float4 b2 = *reinterpret_cast<const float4*>(
                rv + swz128((uint32_t)(vk * 128 + e0 * 4 + 16)));
            const float* fa = reinterpret_cast<const float*>(&a);
            const float* fb = reinterpret_cast<const float*>(&b2);
            #pragma unroll
            for (int j = 0; j < 4; ++j) {
                *reinterpret_cast<__half*>(vf + swz256((uint32_t)((e0 + j) * 256 + vk * 2)))
                    = __float2half_rn(fa[j]);
                *reinterpret_cast<__half*>(vf + swz256((uint32_t)((e0 + 4 + j) * 256 + vk * 2)))
                    = __float2half_rn(fb[j]);
            }
        }
    };

    // ================= Phase 1: S = Q K^T (fp16, cp.async, 1 sync/chunk) =====
    float acc[16][4];
    #pragma unroll
    for (int nt = 0; nt < 16; ++nt)
        #pragma unroll
        for (int cc = 0; cc < 4; ++cc) acc[nt][cc] = 0.f;

    cpstage1(0, 0);
    #pragma unroll 1
    for (int c = 0; c < 8; ++c) {
        if (c < 7) {
            cpstage1(c + 1, (c + 1) & 1);
            cpwait<1>();
        } else {
            // rawV (overlay rawQK[0]) safe: convert1(6) reads ended at barrier 6
            cpstageV(0);
            cpstageV(1);
            cpwait<2>();   // QK7 landed; V0/V1 in flight
        }
        convert1(c & 1);
        __syncthreads();   // fp16[c&1] ready; orders buffer reuse across iters
        const uint32_t bb = sb + BF0 + (c & 1) * 16384;
        #pragma unroll
        for (int ks = 0; ks < 2; ++ks) {
            const int colB = (lc + ks * 16) * 2;
            uint32_t qf[4];
            ldmx4(qf, bb + swz64((uint32_t)((wm * 16 + lr) * 64 + colB)));
            #pragma unroll
            for (int ng = 0; ng < 8; ++ng) {
                if (ng < ngEnd) {
                    uint32_t k4[4];
                    ldmx4(k4, bb + 8192 + swz64((uint32_t)((ng * 16 + lr) * 64 + colB)));
                    mma16816(acc[2 * ng],     qf, k4[0], k4[2]);
                    mma16816(acc[2 * ng + 1], qf, k4[1], k4[3]);
                }
            }
        }
    }

    // ================= Phase 2: shuffle-only softmax =================
    const int nValid = 2 * ngEnd;    // live n8-tiles for this warp
    float rmax[2] = {-INFINITY, -INFINITY};
    #pragma unroll
    for (int nt = 0; nt < 16; ++nt) {
        if (nt < nValid) {
            #pragma unroll
            for (int cc = 0; cc < 4; ++cc) {
                int row = wm * 16 + (cc >> 1) * 8 + g;
                int col = nt * 8 + 2 * tg + (cc & 1);
                float v = (col <= row) ? acc[nt][cc] * SCALE : -INFINITY;
                acc[nt][cc] = v;
                rmax[cc >> 1] = fmaxf(rmax[cc >> 1], v);
            }
        }
    }
    #pragma unroll
    for (int rh = 0; rh < 2; ++rh) {
        rmax[rh] = fmaxf(rmax[rh], __shfl_xor_sync(0xffffffffu, rmax[rh], 1));
        rmax[rh] = fmaxf(rmax[rh], __shfl_xor_sync(0xffffffffu, rmax[rh], 2));
    }
    float rsum[2] = {0.f, 0.f};
    #pragma unroll
    for (int nt = 0; nt < 16; ++nt) {
        if (nt < nValid) {
            #pragma unroll
            for (int cc = 0; cc < 4; ++cc) {
                float p = __expf(acc[nt][cc] - rmax[cc >> 1]);
                acc[nt][cc] = p;
                rsum[cc >> 1] += p;
            }
        } else {
            #pragma unroll
            for (int cc = 0; cc < 4; ++cc) acc[nt][cc] = 0.f;
        }
    }
    #pragma unroll
    for (int rh = 0; rh < 2; ++rh) {
        rsum[rh] += __shfl_xor_sync(0xffffffffu, rsum[rh], 1);
        rsum[rh] += __shfl_xor_sync(0xffffffffu, rsum[rh], 2);
    }
    const float rinv[2] = {1.f / rsum[0], 1.f / rsum[1]};

    // Normalize; A -> gmem (fp32, streaming) and fp16 A-operand fragments IN
    // REGISTERS (C-frag layout == row-major A-frag layout for m16n8k16).
    uint32_t Af[8][4];
    #pragma unroll
    for (int t = 0; t < 8; ++t) {
        #pragma unroll
        for (int half = 0; half < 2; ++half) {
            int nt = 2 * t + half;
            #pragma unroll
            for (int rh = 0; rh < 2; ++rh) {
                float a0 = acc[nt][rh * 2]     * rinv[rh];
                float a1 = acc[nt][rh * 2 + 1] * rinv[rh];
                Af[t][half * 2 + rh] = packh2(a0, a1);
                if (Afl) {
                    int row = wm * 16 + rh * 8 + g;
                    int col = nt * 8 + 2 * tg;
                    stcs2(Afl + ((long)b * Tt + (long)n * BSz + row) * BSz + col, a0, a1);
                }
            }
        }
    }

    // V chunk 0: data landed (own groups) -> convert into VF[0].
    // VF overlays rawQK[1]: last read convert1(7), ordered by barrier 7.
    cpwait<1>();
    convertV(0);
    __syncthreads();   // VF[0] visible to all warps

    // ================= Phase 3: O = A V (8 e-chunks of 32, cp.async pipe) ====
    // Warp wm: rows wm*16..+15, all 32 e of the chunk; skip zero A k-tiles.
    #pragma unroll 1
    for (int nc = 0; nc < 8; ++nc) {
        if (nc + 2 < 8) {
            cpstageV(nc + 2);            // rawV[nc&1]: last read convertV(nc),
            cpwait<1>();                 //   ordered by iter nc-1 barrier
            convertV(nc + 1);
        } else if (nc + 1 < 8) {
            cpwait<0>();
            convertV(nc + 1);
        }
        const uint32_t vb = sb + VF0 + (nc & 1) * 8192;

        float o3[4][4];
        #pragma unroll
        for (int nt = 0; nt < 4; ++nt)
            #pragma unroll
            for (int cc = 0; cc < 4; ++cc) o3[nt][cc] = 0.f;

        #pragma unroll
        for (int ks = 0; ks < 8; ++ks) {
            if (ks < ngEnd) {
                const int colB = (lc + ks * 16) * 2;
                #pragma unroll
                for (int et = 0; et < 2; ++et) {
                    uint32_t v4[4];
                    ldmx4(v4, vb + swz256((uint32_t)((et * 16 + lr) * 256 + colB)));
                    mma16816(o3[2 * et],     Af[ks], v4[0], v4[2]);
                    mma16816(o3[2 * et + 1], Af[ks], v4[1], v4[3]);
                }
            }
        }

        #pragma unroll
        for (int nt = 0; nt < 4; ++nt)
            #pragma unroll
            for (int rh = 0; rh < 2; ++rh) {
                int row = wm * 16 + rh * 8 + g;
                int col = nc * VC + nt * 8 + 2 * tg;
                stcs2(Out + base + (long)row * Ee + col,
                      o3[nt][rh * 2], o3[nt][rh * 2 + 1]);
            }
        __syncthreads();   // VF[(nc+1)&1] staged; this-chunk VF reads done
    }
}

extern "C" void kernel_launch(void* const* d_in, const int* in_sizes, int n_in,
                              void* d_out, int out_size)
{
    const float* Q = (const float*)d_in[0];
    const float* K = (const float*)d_in[1];
    const float* V = (const float*)d_in[2];
    float* out = (float*)d_out;

    const int b = in_sizes[0] / (Tt * Ee);
    const long out_elems = (long)b * Tt * Ee;
    const long a_elems   = (long)b * Tt * BSz;
    float* Afl = ((long)out_size >= out_elems + a_elems) ? (out + out_elems) : nullptr;

    cudaFuncSetAttribute(diag_block_attn_mma,
                         cudaFuncAttributeMaxDynamicSharedMemorySize, SMEM_BYTES);
    dim3 grid(NBk, b);
    diag_block_attn_mma<<<grid, NT, SMEM_BYTES>>>(Q, K, V, out, Afl);
}

// round 15
// speedup vs baseline: 1.0109x; 1.0109x over previous
#include <cuda_runtime.h>
#include <cuda_fp16.h>
#include <cstdint>
#include <math.h>

// DiagBlockAttention b=16,t=8192,e=256,block=128 — mma.sync fp16 single-pass.
// R15: R13 base; Q removed from smem entirely — per-warp direct LDG -> register
// fp16 A-fragments (prefetched one chunk ahead). K keeps cp.async staging.
// d_out = O [b,t,256] fp32 ++ A_flat [b,t,128] fp32.

namespace {
constexpr int Tt = 8192, Ee = 256, BSz = 128, NBk = 64;
constexpr float SCALE = 0.0625f;
constexpr int EC = 32;           // phase-1 e-chunk
constexpr int VC = 32;           // phase-3 e-chunk
constexpr int NT = 256;

// SMEM byte map
// fp16 K tiles [128 r][32 c], 64B rows (swz64), double buffered: BF0 + bs*8192
constexpr int BF0  = 0;
// raw fp32 K staging, double-buffered: RAW0 + bs*16384
constexpr int RAW0 = 16384;
// V^T fp16 [32 e][128 tok], 256B rows (swz256), double buffered: VF0 + bs*8192
constexpr int VF0  = 49152;
constexpr int SMEM_BYTES = 65536;   // 64 KB -> 2 CTAs/SM (reg-capped anyway)
}

__device__ __forceinline__ uint32_t swz64(uint32_t o)  { return o ^ ((o >> 3) & 0x30u); }
__device__ __forceinline__ uint32_t swz256(uint32_t o) { return o ^ ((o >> 4) & 0x70u); }

__device__ __forceinline__ uint32_t smem_u32(const void* p) {
    uint32_t a;
    asm("{ .reg .u64 t; cvta.to.shared.u64 t, %1; cvt.u32.u64 %0, t; }" : "=r"(a) : "l"(p));
    return a;
}

__device__ __forceinline__ void cpasync16(uint32_t dst, const void* src) {
    asm volatile("cp.async.ca.shared.global [%0], [%1], 16;" :: "r"(dst), "l"(src) : "memory");
}
__device__ __forceinline__ void cpcommit() {
    asm volatile("cp.async.commit_group;" ::: "memory");
}
template <int N>
__device__ __forceinline__ void cpwait() {
    asm volatile("cp.async.wait_group %0;" :: "n"(N) : "memory");
}

__device__ __forceinline__ void ldmx4(uint32_t r[4], uint32_t addr) {
    asm volatile("ldmatrix.sync.aligned.m8n8.x4.shared.b16 {%0,%1,%2,%3}, [%4];"
                 : "=r"(r[0]), "=r"(r[1]), "=r"(r[2]), "=r"(r[3]) : "r"(addr));
}

__device__ __forceinline__ void mma16816(float c[4], const uint32_t a[4],
                                         uint32_t b0, uint32_t b1) {
    asm volatile("mma.sync.aligned.m16n8k16.row.col.f32.f16.f16.f32 "
                 "{%0,%1,%2,%3},{%4,%5,%6,%7},{%8,%9},{%0,%1,%2,%3};"
                 : "+f"(c[0]), "+f"(c[1]), "+f"(c[2]), "+f"(c[3])
                 : "r"(a[0]), "r"(a[1]), "r"(a[2]), "r"(a[3]), "r"(b0), "r"(b1));
}

// Pack two fp32 into fp16x2 (lo = x, hi = y), round-to-nearest.
__device__ __forceinline__ uint32_t packh2(float x, float y) {
    uint32_t r;
    asm("cvt.rn.f16x2.f32 %0, %1, %2;" : "=r"(r) : "f"(y), "f"(x));
    return r;
}

__global__ void __launch_bounds__(NT, 2)
diag_block_attn_mma(const float* __restrict__ Q, const float* __restrict__ K,
                    const float* __restrict__ V, float* __restrict__ Out,
                    float* __restrict__ Afl)
{
    extern __shared__ char smc[];
    const uint32_t sb = smem_u32(smc);

    const int tid = threadIdx.x;
    const int wid = tid >> 5;        // 0..7
    const int lid = tid & 31;
    const int g   = lid >> 2;
    const int tg  = lid & 3;
    const int wm  = wid;             // warp row band: rows wm*16..+15
    const int lr  = lid & 15;
    const int lc  = (lid >> 4) * 8;  // ldmatrix col-block (elements)
    const int n   = blockIdx.x;
    const int b   = blockIdx.y;
    const long base = ((long)b * Tt + (long)n * BSz) * Ee;

    // Causal: 16-wide col-tile ng kept iff ng <= wm (also phase-3 k-tiles).
    const int ngEnd = wm + 1;

    // Q row pointers for this thread's A-fragment rows.
    const float* Qr0 = Q + base + (long)(wm * 16 + g) * Ee;
    const float* Qr8 = Qr0 + 8 * Ee;

    // ---- Q: raw LDG of chunk c's A-frag elements (8 float2) ----
    auto ldQ = [&](int c, float2 qr[8]) {
        const int cb = c * EC + 2 * tg;
        #pragma unroll
        for (int ks = 0; ks < 2; ++ks) {
            int cc = cb + ks * 16;
            qr[4 * ks + 0] = *reinterpret_cast<const float2*>(Qr0 + cc);
            qr[4 * ks + 1] = *reinterpret_cast<const float2*>(Qr8 + cc);
            qr[4 * ks + 2] = *reinterpret_cast<const float2*>(Qr0 + cc + 8);
            qr[4 * ks + 3] = *reinterpret_cast<const float2*>(Qr8 + cc + 8);
        }
    };
    // ---- Q: pack raw float2s into fp16 A-fragments Qf[2][4] ----
    auto cvtQ = [&](const float2 qr[8], uint32_t Qf[2][4]) {
        #pragma unroll
        for (int ks = 0; ks < 2; ++ks)
            #pragma unroll
            for (int j = 0; j < 4; ++j)
                Qf[ks][j] = packh2(qr[4 * ks + j].x, qr[4 * ks + j].y);
    };

    // ---- K: cp.async raw fp32 chunk c -> raw buffer bs ----
    auto cpstageK = [&](int c, int bs) {
        const float* Kg = K + base + c * EC;
        const uint32_t rw = sb + RAW0 + bs * 16384;
        #pragma unroll
        for (int u = 0; u < 4; ++u) {
            int idx = tid + NT * u;        // 0..1023
            int r   = idx >> 3;            // 0..127
            int s   = idx & 7;             // 16B segment
            cpasync16(rw + r * 128 + s * 16, Kg + (long)r * Ee + s * 4);
        }
        cpcommit();
    };
    // ---- K: convert raw buffer bs -> fp16 tile buffer bs (same idx map) ----
    auto convertK = [&](int bs) {
        const char* rw = smc + RAW0 + bs * 16384;
        char* fb = smc + BF0 + bs * 8192;
        #pragma unroll
        for (int u = 0; u < 4; ++u) {
            int idx = tid + NT * u;        // 0..1023
            int r   = idx >> 3;
            int ce  = (idx & 7) << 2;
            float4 k = *reinterpret_cast<const float4*>(rw + r * 128 + ce * 4);
            uint32_t off = swz64((uint32_t)(r * 64 + ce * 2));
            *reinterpret_cast<uint2*>(fb + off) =
                make_uint2(packh2(k.x, k.y), packh2(k.z, k.w));
        }
    };

    // ---- phase-3 V: per-thread coords (unit u in {0,1}) ----
    auto vcoord = [&](int u, int& k, int& e0) {
        int unit = tid + NT * u;        // 0..511
        int l    = unit & 31;
        int grp  = unit >> 5;           // 0..15
        k  = 2 * l + 64 * (grp >> 3);
        e0 = 4 * (grp & 7);
    };
    auto ldV = [&](int nc, float4 pv[4]) {
        #pragma unroll
        for (int u = 0; u < 2; ++u) {
            int k, e0; vcoord(u, k, e0);
            const float* vg = V + base + (long)k * Ee + nc * VC + e0;
            pv[2 * u]     = *reinterpret_cast<const float4*>(vg);
            pv[2 * u + 1] = *reinterpret_cast<const float4*>(vg + Ee);
        }
    };
    auto stV = [&](int bs, const float4 pv[4]) {
        char* bb = smc + VF0 + bs * 8192;
        #pragma unroll
        for (int u = 0; u < 2; ++u) {
            int k, e0; vcoord(u, k, e0);
            const float* a0 = reinterpret_cast<const float*>(&pv[2 * u]);
            const float* a1 = reinterpret_cast<const float*>(&pv[2 * u + 1]);
            #pragma unroll
            for (int j = 0; j < 4; ++j) {
                uint32_t off = swz256((uint32_t)((e0 + j) * 256 + k * 2));
                *reinterpret_cast<uint32_t*>(bb + off) = packh2(a0[j], a1[j]);
            }
        }
    };

    // ================= Phase 1: S = Q K^T (fp16, 1 sync/chunk) ==============
    float acc[16][4];
    #pragma unroll
    for (int nt = 0; nt < 16; ++nt)
        #pragma unroll
        for (int cc = 0; cc < 4; ++cc) acc[nt][cc] = 0.f;

    float2 qraw[8];
    uint32_t Qf[2][4];
    ldQ(0, qraw);
    cpstageK(0, 0);
    cvtQ(qraw, Qf);
    #pragma unroll 1
    for (int c = 0; c < 8; ++c) {
        if (c + 1 < 8) {
            ldQ(c + 1, qraw);               // LDG latency covered by MMAs below
            cpstageK(c + 1, (c + 1) & 1);
            cpwait<1>();
        } else {
            cpwait<0>();
        }
        convertK(c & 1);
        __syncthreads();   // fp16 K[c&1] ready; orders buffer reuse (see R13)
        const uint32_t bb = sb + BF0 + (c & 1) * 8192;
        #pragma unroll
        for (int ks = 0; ks < 2; ++ks) {
            const int colB = (lc + ks * 16) * 2;
            #pragma unroll
            for (int ng = 0; ng < 8; ++ng) {
                if (ng < ngEnd) {
                    uint32_t k4[4];
                    ldmx4(k4, bb + swz64((uint32_t)((ng * 16 + lr) * 64 + colB)));
                    mma16816(acc[2 * ng],     Qf[ks], k4[0], k4[2]);
                    mma16816(acc[2 * ng + 1], Qf[ks], k4[1], k4[3]);
                }
            }
        }
        if (c + 1 < 8) cvtQ(qraw, Qf);      // raw(c+1) landed during MMAs
    }

    // ================= Phase 2: shuffle-only softmax =================
    const int nValid = 2 * ngEnd;    // live n8-tiles for this warp
    float rmax[2] = {-INFINITY, -INFINITY};
    #pragma unroll
    for (int nt = 0; nt < 16; ++nt) {
        if (nt < nValid) {
            #pragma unroll
            for (int cc = 0; cc < 4; ++cc) {
                int row = wm * 16 + (cc >> 1) * 8 + g;
                int col = nt * 8 + 2 * tg + (cc & 1);
                float v = (col <= row) ? acc[nt][cc] * SCALE : -INFINITY;
                acc[nt][cc] = v;
                rmax[cc >> 1] = fmaxf(rmax[cc >> 1], v);
            }
        }
    }
    #pragma unroll
    for (int rh = 0; rh < 2; ++rh) {
        rmax[rh] = fmaxf(rmax[rh], __shfl_xor_sync(0xffffffffu, rmax[rh], 1));
        rmax[rh] = fmaxf(rmax[rh], __shfl_xor_sync(0xffffffffu, rmax[rh], 2));
    }
    float rsum[2] = {0.f, 0.f};
    #pragma unroll
    for (int nt = 0; nt < 16; ++nt) {
        if (nt < nValid) {
            #pragma unroll
            for (int cc = 0; cc < 4; ++cc) {
                float p = __expf(acc[nt][cc] - rmax[cc >> 1]);
                acc[nt][cc] = p;
                rsum[cc >> 1] += p;
            }
        } else {
            #pragma unroll
            for (int cc = 0; cc < 4; ++cc) acc[nt][cc] = 0.f;
        }
    }
    #pragma unroll
    for (int rh = 0; rh < 2; ++rh) {
        rsum[rh] += __shfl_xor_sync(0xffffffffu, rsum[rh], 1);
        rsum[rh] += __shfl_xor_sync(0xffffffffu, rsum[rh], 2);
    }
    const float rinv[2] = {1.f / rsum[0], 1.f / rsum[1]};

    // Pre-stage V chunk 0; LDG latency hides behind the A-frag build below.
    {
        float4 pv[4];
        ldV(0, pv);

        // Normalize; A -> gmem (fp32) and fp16 A-operand fragments IN REGS
        // (C-frag layout == row-major A-frag layout for m16n8k16).
        uint32_t Af[8][4];
        #pragma unroll
        for (int t = 0; t < 8; ++t) {
            #pragma unroll
            for (int half = 0; half < 2; ++half) {
                int nt = 2 * t + half;
                #pragma unroll
                for (int rh = 0; rh < 2; ++rh) {
                    float a0 = acc[nt][rh * 2]     * rinv[rh];
                    float a1 = acc[nt][rh * 2 + 1] * rinv[rh];
                    Af[t][half * 2 + rh] = packh2(a0, a1);
                    if (Afl) {
                        int row = wm * 16 + rh * 8 + g;
                        int col = nt * 8 + 2 * tg;
                        *reinterpret_cast<float2*>(
                            Afl + ((long)b * Tt + (long)n * BSz + row) * BSz + col) =
                            make_float2(a0, a1);
                    }
                }
            }
        }
        stV(0, pv);
        __syncthreads();   // V chunk 0 staged; all warps past phase-1 reads

        // ============== Phase 3: O = A V (8 chunks, reg-prefetched) ==========
        #pragma unroll 1
        for (int nc = 0; nc < 8; ++nc) {
            float4 pnext[4];
            if (nc + 1 < 8) ldV(nc + 1, pnext);   // latency covered by MMAs
            const uint32_t vb = sb + VF0 + (nc & 1) * 8192;

            float o3[4][4];
            #pragma unroll
            for (int nt = 0; nt < 4; ++nt)
                #pragma unroll
                for (int cc = 0; cc < 4; ++cc) o3[nt][cc] = 0.f;

            #pragma unroll
            for (int ks = 0; ks < 8; ++ks) {
                if (ks < ngEnd) {
                    const int colB = (lc + ks * 16) * 2;
                    #pragma unroll
                    for (int et = 0; et < 2; ++et) {
                        uint32_t v4[4];
                        ldmx4(v4, vb + swz256((uint32_t)((et * 16 + lr) * 256 + colB)));
                        mma16816(o3[2 * et],     Af[ks], v4[0], v4[2]);
                        mma16816(o3[2 * et + 1], Af[ks], v4[1], v4[3]);
                    }
                }
            }

            if (nc + 1 < 8) stV((nc + 1) & 1, pnext);

            #pragma unroll
            for (int nt = 0; nt < 4; ++nt)
                #pragma unroll
                for (int rh = 0; rh < 2; ++rh) {
                    int row = wm * 16 + rh * 8 + g;
                    int col = nc * VC + nt * 8 + 2 * tg;
                    *reinterpret_cast<float2*>(Out + base + (long)row * Ee + col) =
                        make_float2(o3[nt][rh * 2], o3[nt][rh * 2 + 1]);
                }
            __syncthreads();   // next-chunk V staged; this-chunk reads done
        }
    }
}

extern "C" void kernel_launch(void* const* d_in, const int* in_sizes, int n_in,
                              void* d_out, int out_size)
{
    const float* Q = (const float*)d_in[0];
    const float* K = (const float*)d_in[1];
    const float* V = (const float*)d_in[2];
    float* out = (float*)d_out;

    const int b = in_sizes[0] / (Tt * Ee);
    const long out_elems = (long)b * Tt * Ee;
    const long a_elems   = (long)b * Tt * BSz;
    float* Afl = ((long)out_size >= out_elems + a_elems) ? (out + out_elems) : nullptr;

    cudaFuncSetAttribute(diag_block_attn_mma,
                         cudaFuncAttributeMaxDynamicSharedMemorySize, SMEM_BYTES);
    dim3 grid(NBk, b);
    diag_block_attn_mma<<<grid, NT, SMEM_BYTES>>>(Q, K, V, out, Afl);
}